// round 12
// baseline (speedup 1.0000x reference)
#include <cuda_runtime.h>
#include <cstdint>

#define D_DIM   50257
#define B_Q     64
#define K_A     4096
#define KNN     8
#define EPSF    1e-10f
#define LN2F    0.69314718055994530942f

#define DSPLIT  9
#define DTILE   32
#define STAGES  175                  // ceil(50257 / (9*32))
#define CHUNK_D (STAGES * DTILE)     // 5600
#define DPAD    (DSPLIT * CHUNK_D)   // 50400
#define NTILES  (DPAD / DTILE)       // 1575
#define KTILE   128

#define QSCALE  680.0f               // qlog quantization scale (Q fits 15 bits signed)
#define COMB_INV (1.0 / (16384.0 * 680.0))

// ---- static device scratch ----
// per 32-d tile: 4KB = [Q1 fragments 2KB][Q2 fragments 2KB], already in MMA B-fragment order
__device__ __align__(16) uint32_t g_qB[NTILES * 1024];   // 6.4 MB
__device__ float g_cross[DSPLIT * B_Q * K_A];            // 9.4 MB partial cross sums (D-units)
__device__ float g_self [DSPLIT * K_A];

__device__ __forceinline__ uint32_t smem_u32(const void* p) {
    uint32_t a;
    asm("{ .reg .u64 t; cvta.to.shared.u64 t, %1; cvt.u32.u64 %0, t; }" : "=r"(a) : "l"(p));
    return a;
}

#define CP_ASYNC16(dst, src) asm volatile("cp.async.cg.shared.global [%0], [%1], 16;" :: "r"(dst), "l"(src))
#define CP_COMMIT()          asm volatile("cp.async.commit_group;" ::: "memory")
#define CP_WAIT0()           asm volatile("cp.async.wait_group 0;" ::: "memory")

#define LDSM_X4(r, a) \
    asm volatile("ldmatrix.sync.aligned.m8n8.x4.shared.b16 {%0,%1,%2,%3}, [%4];" \
        : "=r"((r)[0]),"=r"((r)[1]),"=r"((r)[2]),"=r"((r)[3]) : "r"(a))

#define MMA_S8(c, a, b0, b1) \
    asm volatile("mma.sync.aligned.m16n8k32.row.col.s32.s8.s8.s32 " \
        "{%0,%1,%2,%3}, {%4,%5,%6,%7}, {%8,%9}, {%0,%1,%2,%3};" \
        : "+r"((c)[0]),"+r"((c)[1]),"+r"((c)[2]),"+r"((c)[3]) \
        : "r"((a)[0]),"r"((a)[1]),"r"((a)[2]),"r"((a)[3]), "r"(b0),"r"(b1))

// ---------------- Kernel A: qlog -> two s8 limbs, emitted in MMA B-fragment order ----------------
// Fragment (m16n8k32, col-major B): lane l of group g holds b0 = Q[col=l>>2][k=4(l&3)+0..3],
// b1 = Q[col][k=16+4(l&3)+0..3]. We store per tile t: Q1 plane then Q2 plane, each
// [group g][lane l] -> uint2 {b0,b1} at g*256 + l*8 bytes.
__global__ void __launch_bounds__(256)
qlog_kernel(const float* __restrict__ q) {
    const int t    = blockIdx.x;
    const int g    = threadIdx.x >> 5;          // query group (8 queries)
    const int l    = threadIdx.x & 31;
    const int b    = 8 * g + (l >> 2);          // query index
    const int kloc = 4 * (l & 3);

    uint32_t p1[2], p2[2];
#pragma unroll
    for (int h = 0; h < 2; ++h) {               // b0 / b1 halves
        uint32_t w1 = 0, w2 = 0;
#pragma unroll
        for (int j = 0; j < 4; ++j) {
            const int d = t * DTILE + 16 * h + kloc + j;
            int Q = 0;
            if (d < D_DIM) {
                float x = __log2f(q[(size_t)b * D_DIM + d] + EPSF) * LN2F;
                Q = __float2int_rn(x * QSCALE);
            }
            int Q1 = Q >> 7;                    // arithmetic: in [-123, 3]
            int Q2 = Q - (Q1 << 7);             // in [0, 127]
            w1 |= (uint32_t)(Q1 & 0xFF) << (8 * j);
            w2 |= (uint32_t)(Q2 & 0xFF) << (8 * j);
        }
        p1[h] = w1; p2[h] = w2;
    }
    uint32_t* tb = g_qB + (size_t)t * 1024;
    uint2* o1 = reinterpret_cast<uint2*>(tb)       + g * 32 + l;
    uint2* o2 = reinterpret_cast<uint2*>(tb + 512) + g * 32 + l;
    *o1 = make_uint2(p1[0], p1[1]);
    *o2 = make_uint2(p2[0], p2[1]);
}

// ---------------- Kernel B: int8 IMMA two-limb GEMM + fused exact-fp32 self-term ----------------
// smem: A bufs at 0/8192 (each: A1 128x32 s8 = 4KB, A2 at +4096); B bufs at 16384/20480 (4KB each).
// Epilogue reuses smem as 64x128 float (32KB).
__global__ void __launch_bounds__(256, 2)
gemm_kernel(const float* __restrict__ anchor) {
    __shared__ __align__(128) char smem[32768];
    const uint32_t sb = smem_u32(smem);

    const int tid  = threadIdx.x;
    const int lane = tid & 31;
    const int wid  = tid >> 5;
    const int wm   = wid >> 1;        // 0..3 : 32-row M tile
    const int wn   = wid & 1;         // 0..1 : 32-col N tile
    const int kb   = blockIdx.x * KTILE;
    const int cI   = blockIdx.y;
    const int dbase = cI * CHUNK_D;

    // loader: lane -> row sub r0 = lane>>3 (0..3), 4 consecutive d at 4*(lane&7)
    const int r0 = lane >> 3;
    const int c4 = 4 * (lane & 7);

    int acc1[2][4][4], acc2[2][4][4];
#pragma unroll
    for (int mi = 0; mi < 2; ++mi)
#pragma unroll
        for (int j = 0; j < 4; ++j)
#pragma unroll
            for (int r = 0; r < 4; ++r) { acc1[mi][j][r] = 0; acc2[mi][j][r] = 0; }

    float selfAcc[4];
#pragma unroll
    for (int i = 0; i < 4; ++i) selfAcc[i] = 0.f;

    float va[4][4];

    auto loadA = [&](int s) {
        const int d0 = dbase + s * DTILE + c4;
#pragma unroll
        for (int i = 0; i < 4; ++i) {
            const float* p = anchor + (size_t)(kb + wid * 16 + 4 * i + r0) * D_DIM + d0;
#pragma unroll
            for (int j = 0; j < 4; ++j)
                va[i][j] = (d0 + j < D_DIM) ? __ldg(p + j) : 0.f;
        }
    };
    auto storeA = [&](int buf) {
        const uint32_t aB = (uint32_t)buf * 8192;
#pragma unroll
        for (int i = 0; i < 4; ++i) {
            const int r = wid * 16 + 4 * i + r0;
            uint32_t w1 = 0, w2 = 0;
#pragma unroll
            for (int j = 0; j < 4; ++j) {
                float x = va[i][j];
                selfAcc[i] += x * __log2f(x + EPSF);        // exact-fp32 self term
                int A = __float2int_rn(x * 16384.f);
                A = min(A, 16383);                          // a in [0,1): clamp edge
                int A1 = A >> 7;                            // [0,127]
                int A2 = A & 127;                           // [0,127]
                w1 |= (uint32_t)A1 << (8 * j);
                w2 |= (uint32_t)A2 << (8 * j);
            }
            // swizzled STS.32: row r (32B), 16B chunk c' = c ^ ((r>>2)&1)
            uint32_t c  = (uint32_t)((lane & 7) >> 2);
            uint32_t byte = (uint32_t)r * 32 + ((c ^ (((uint32_t)r >> 2) & 1)) << 4) + ((lane & 3) << 2);
            *(uint32_t*)(smem + aB + byte)        = w1;
            *(uint32_t*)(smem + aB + 4096 + byte) = w2;
        }
    };
    auto issueB = [&](int s, int buf) {
        const char* src = reinterpret_cast<const char*>(g_qB) + (size_t)(cI * STAGES + s) * 4096;
        CP_ASYNC16(sb + 16384 + buf * 4096 + tid * 16, src + tid * 16);
    };

    // ldmatrix A lane constants: row = R + (lane&7) + ((lane>>3)&1)*8, half = lane>>4
    const int lrow = (lane & 7) + ((lane >> 3) & 1) * 8;
    const int lhalf = lane >> 4;

    // prologue
    loadA(0);
    issueB(0, 0);
    CP_COMMIT();
    storeA(0);
    CP_WAIT0();
    __syncthreads();

    for (int s = 0; s < STAGES; ++s) {
        const int buf = s & 1;
        const bool more = (s + 1 < STAGES);
        if (more) {
            loadA(s + 1);
            issueB(s + 1, buf ^ 1);
            CP_COMMIT();
        }

        const uint32_t aB = sb + (uint32_t)buf * 8192;
        const uint32_t bB = sb + 16384 + (uint32_t)buf * 4096;

        uint32_t a1f[2][4], a2f[2][4], q1f[4][2], q2f[4][2];
#pragma unroll
        for (int mi = 0; mi < 2; ++mi) {
            const int row = wm * 32 + mi * 16 + lrow;
            uint32_t addr = aB + (uint32_t)row * 32
                          + ((uint32_t)(lhalf ^ ((row >> 2) & 1)) << 4);
            LDSM_X4(a1f[mi], addr);
            LDSM_X4(a2f[mi], addr + 4096);
        }
#pragma unroll
        for (int j = 0; j < 4; ++j) {
            const uint32_t go = (uint32_t)(4 * wn + j) * 256 + (uint32_t)lane * 8;
            uint2 v1 = *(const uint2*)(smem + (bB - sb) + go);
            uint2 v2 = *(const uint2*)(smem + (bB - sb) + 2048 + go);
            q1f[j][0] = v1.x; q1f[j][1] = v1.y;
            q2f[j][0] = v2.x; q2f[j][1] = v2.y;
        }
        // product-major issue: same-accumulator spacing = 8 MMAs
#pragma unroll
        for (int mi = 0; mi < 2; ++mi)
#pragma unroll
            for (int j = 0; j < 4; ++j)
                MMA_S8(acc1[mi][j], a1f[mi], q1f[j][0], q1f[j][1]);
#pragma unroll
        for (int mi = 0; mi < 2; ++mi)
#pragma unroll
            for (int j = 0; j < 4; ++j)
                MMA_S8(acc2[mi][j], a1f[mi], q2f[j][0], q2f[j][1]);
#pragma unroll
        for (int mi = 0; mi < 2; ++mi)
#pragma unroll
            for (int j = 0; j < 4; ++j)
                MMA_S8(acc2[mi][j], a2f[mi], q1f[j][0], q1f[j][1]);

        if (more) storeA(buf ^ 1);
        CP_WAIT0();
        __syncthreads();
    }

    // ---- self-term: reduce the 8 lanes (lane&7) sharing each row ----
#pragma unroll
    for (int i = 0; i < 4; ++i) {
        float v = selfAcc[i];
        v += __shfl_xor_sync(0xffffffffu, v, 1);
        v += __shfl_xor_sync(0xffffffffu, v, 2);
        v += __shfl_xor_sync(0xffffffffu, v, 4);
        if ((lane & 7) == 0)
            g_self[cI * K_A + kb + wid * 16 + 4 * i + r0] = v * LN2F;
    }
    __syncthreads();   // done reading A/B smem before epilogue overwrite

    // ---- epilogue: combine limbs, transpose through smem, coalesced stores ----
    float* Csm = reinterpret_cast<float*>(smem);   // [64 q][128 m]
    const int cg  = lane >> 2;
    const int tig = lane & 3;
#pragma unroll
    for (int mi = 0; mi < 2; ++mi) {
        const int r = wm * 32 + mi * 16 + cg;
#pragma unroll
        for (int j = 0; j < 4; ++j) {
            const int col = wn * 32 + j * 8 + tig * 2;
#pragma unroll
            for (int rr = 0; rr < 4; ++rr) {
                double v = ((double)acc1[mi][j][rr] * 16384.0
                          + (double)acc2[mi][j][rr] * 128.0) * COMB_INV;
                const int row = r + (rr >> 1) * 8;
                const int cc  = col + (rr & 1);
                Csm[cc * 128 + row] = (float)v;
            }
        }
    }
    __syncthreads();
    {
        const int qq = tid >> 2;
        const int mb = (tid & 3) * 32;
        const float4* src = reinterpret_cast<const float4*>(Csm + qq * 128 + mb);
        float4* dst = reinterpret_cast<float4*>(g_cross + ((size_t)(cI * B_Q + qq)) * K_A + kb + mb);
#pragma unroll
        for (int j = 0; j < 8; ++j) dst[j] = src[j];
    }
}

// ---------------- Kernel C: fp64 combine + top-8 argmin + majority vote ----------------
__global__ void __launch_bounds__(256)
topk_kernel(const int* __restrict__ label, float* __restrict__ out) {
    __shared__ double kl[K_A];
    __shared__ double rv[256];
    __shared__ int    ri[256];
    const int b   = blockIdx.x;
    const int tid = threadIdx.x;

    for (int k = tid; k < K_A; k += 256) {
        double s = 0.0;
#pragma unroll
        for (int c = 0; c < DSPLIT; ++c)
            s += (double)g_self[c * K_A + k]
               - (double)g_cross[((size_t)(c * B_Q + b)) * K_A + k];
        kl[k] = s;   // = D * kl[b][k]
    }
    __syncthreads();

    int cnt1 = 0;
    for (int r = 0; r < KNN; ++r) {
        double bv = 1e300; int bi = K_A - 1;
        for (int k = tid; k < K_A; k += 256) {
            double v = kl[k];
            if (v < bv) { bv = v; bi = k; }
        }
        rv[tid] = bv; ri[tid] = bi;
        __syncthreads();
        for (int off = 128; off > 0; off >>= 1) {
            if (tid < off) {
                double v = rv[tid + off]; int i2 = ri[tid + off];
                if (v < rv[tid] || (v == rv[tid] && i2 < ri[tid])) { rv[tid] = v; ri[tid] = i2; }
            }
            __syncthreads();
        }
        int sel = ri[0];
        if (sel < 0)    sel = 0;
        if (sel >= K_A) sel = K_A - 1;
        cnt1 += label[sel];
        if (tid == 0) kl[sel] = 1e300;
        __syncthreads();
    }
    if (tid == 0) out[b] = (cnt1 > KNN / 2) ? 1.0f : 0.0f;
}

extern "C" void kernel_launch(void* const* d_in, const int* in_sizes, int n_in,
                              void* d_out, int out_size) {
    (void)in_sizes; (void)n_in; (void)out_size;
    const float* query  = (const float*)d_in[0];
    const float* anchor = (const float*)d_in[1];
    const int*   label  = (const int*)d_in[2];
    float* out = (float*)d_out;

    qlog_kernel<<<NTILES, 256>>>(query);
    dim3 g(K_A / KTILE, DSPLIT);
    gemm_kernel<<<g, 256>>>(anchor);
    topk_kernel<<<B_Q, 256>>>(label, out);
}

// round 13
// speedup vs baseline: 2.0700x; 2.0700x over previous
#include <cuda_runtime.h>
#include <cuda_bf16.h>
#include <cstdint>

#define D_DIM   50257
#define B_Q     64
#define K_A     4096
#define KNN     8
#define EPSF    1e-10f
#define LN2F    0.69314718055994530942f

#define DSPLIT  9
#define DTILE   32
#define STAGES  175                  // ceil(50257 / (9*32))
#define CHUNK_D (STAGES * DTILE)     // 5600
#define DPAD    (DSPLIT * CHUNK_D)   // 50400
#define NTILES  (DPAD / DTILE)       // 1575
#define KTILE   128

// ---- static device scratch ----
__device__ __align__(16) unsigned short g_qB[NTILES * 4096]; // 12.9MB: per 32-d tile [qh 4KB][ql 4KB], swizzled
__device__ float g_cross[DSPLIT * B_Q * K_A];                // 9.4MB partial cross sums
__device__ float g_self [DSPLIT * K_A];

__device__ __forceinline__ uint32_t smem_u32(const void* p) {
    uint32_t a;
    asm("{ .reg .u64 t; cvta.to.shared.u64 t, %1; cvt.u32.u64 %0, t; }" : "=r"(a) : "l"(p));
    return a;
}

#define CP_ASYNC16(dst, src) asm volatile("cp.async.cg.shared.global [%0], [%1], 16;" :: "r"(dst), "l"(src))
#define CP_COMMIT()          asm volatile("cp.async.commit_group;" ::: "memory")
#define CP_WAIT0()           asm volatile("cp.async.wait_group 0;" ::: "memory")

#define LDSM_X4(r, a) \
    asm volatile("ldmatrix.sync.aligned.m8n8.x4.shared.b16 {%0,%1,%2,%3}, [%4];" \
        : "=r"((r)[0]),"=r"((r)[1]),"=r"((r)[2]),"=r"((r)[3]) : "r"(a))
#define LDSM_X4T(r, a) \
    asm volatile("ldmatrix.sync.aligned.m8n8.x4.trans.shared.b16 {%0,%1,%2,%3}, [%4];" \
        : "=r"((r)[0]),"=r"((r)[1]),"=r"((r)[2]),"=r"((r)[3]) : "r"(a))

#define MMA16816(c, a, b0, b1) \
    asm volatile("mma.sync.aligned.m16n8k16.row.col.f32.bf16.bf16.f32 " \
        "{%0,%1,%2,%3}, {%4,%5,%6,%7}, {%8,%9}, {%0,%1,%2,%3};" \
        : "+f"((c)[0]),"+f"((c)[1]),"+f"((c)[2]),"+f"((c)[3]) \
        : "r"((a)[0]),"r"((a)[1]),"r"((a)[2]),"r"((a)[3]), "r"(b0),"r"(b1))

// ---------------- Kernel A: qlog -> bf16 hi/lo tiles, smem-staged coalesced output ----------------
// One block per 32-d tile. Output layout per tile (8KB): hi rows k=0..31 (128B of 64 n),
// 16B chunk c stored at c^(k&7); lo at +4096B. Matches GEMM's B-side ldmatrix swizzle.
// smem staging rows padded to 72 u16 (144B): bank = 4*lane mod 32 -> 4-way (was 32-way at 64).
#define QPAD 72
__global__ void __launch_bounds__(256)
qlog_kernel(const float* __restrict__ q) {
    __shared__ __align__(16) unsigned short sh[32 * QPAD];
    __shared__ __align__(16) unsigned short sl[32 * QPAD];
    const int t    = blockIdx.x;
    const int lane = threadIdx.x & 31;
    const int w    = threadIdx.x >> 5;
    const int d    = t * DTILE + lane;
    const bool v   = d < D_DIM;
#pragma unroll
    for (int i = 0; i < 8; ++i) {
        const int b = w * 8 + i;
        float x = 0.f;
        if (v) x = __log2f(q[(size_t)b * D_DIM + d] + EPSF) * LN2F;   // coalesced 128B reads
        __nv_bfloat16 h = __float2bfloat16(x);
        __nv_bfloat16 l = __float2bfloat16(x - __bfloat162float(h));
        sh[lane * QPAD + b] = __bfloat16_as_ushort(h);
        sl[lane * QPAD + b] = __bfloat16_as_ushort(l);
    }
    __syncthreads();
    // write out: thread -> one 16B chunk; consecutive tid -> consecutive 16B (fully coalesced)
    const int k  = threadIdx.x >> 3;
    const int cs = threadIdx.x & 7;       // stored chunk
    const int c  = cs ^ (k & 7);          // source b-chunk (involution)
    uint4* tb = reinterpret_cast<uint4*>(g_qB + (size_t)t * 4096);
    tb[k * 8 + cs]       = *reinterpret_cast<const uint4*>(sh + k * QPAD + c * 8);
    tb[256 + k * 8 + cs] = *reinterpret_cast<const uint4*>(sl + k * QPAD + c * 8);
}

// ---------------- Kernel B: bf16 3-chain tensor-core GEMM + fused self-term ----------------
// smem 48KB: A [2 buf][hi|lo][128 r][32 k] bf16 (buf 16KB), B at +32768 [2 buf][hi|lo][32 k][64 n]
// Warp grid 4x2: warp tile 32(M) x 32(N).
__global__ void __launch_bounds__(256, 2)
gemm_kernel(const float* __restrict__ anchor) {
    __shared__ __align__(128) char smem[49152];
    const uint32_t sA = smem_u32(smem);
    const uint32_t sB = sA + 32768;

    const int tid  = threadIdx.x;
    const int lane = tid & 31;
    const int wid  = tid >> 5;
    const int wm   = wid >> 1;        // 0..3 : M quarter (32 rows)
    const int wn   = wid & 1;         // 0..1 : N half (32 cols)
    const int kb   = blockIdx.x * KTILE;
    const int cI   = blockIdx.y;
    const int dbase = cI * CHUNK_D;

    // loader mapping: warp owns rows wid*16..+15; lane: lrow = lane>>4, d-pair = lane&15
    const int lrow = lane >> 4;
    const int lcol = lane & 15;

    // ldmatrix lane constants
    const int rowA = lane & 15;
    const int cA   = lane >> 4;
    const int swzA = ((lane & 15) >> 1) & 3;
    const int kB   = lane & 15;
    const int cB   = lane >> 4;
    const int swzB = lane & 7;

    float acc[2][4][4];               // [mi][nh][frag]
#pragma unroll
    for (int mi = 0; mi < 2; ++mi)
#pragma unroll
        for (int nh = 0; nh < 4; ++nh)
#pragma unroll
            for (int r = 0; r < 4; ++r) acc[mi][nh][r] = 0.f;

    float selfAcc[8];
#pragma unroll
    for (int i = 0; i < 8; ++i) selfAcc[i] = 0.f;

    float2 va[8];

    auto loadA = [&](int s) {
        const int d0 = dbase + s * DTILE + 2 * lcol;
        const bool vx = d0 < D_DIM;
        const bool vy = d0 + 1 < D_DIM;
#pragma unroll
        for (int i = 0; i < 8; ++i) {
            const float* p = anchor + (size_t)(kb + wid * 16 + 2 * i + lrow) * D_DIM + d0;
            va[i].x = vx ? __ldg(p)     : 0.f;
            va[i].y = vy ? __ldg(p + 1) : 0.f;
        }
    };
    auto storeA = [&](int buf) {
        const uint32_t coff   = (uint32_t)(lcol >> 2);
        const uint32_t within = (uint32_t)(lcol & 3) * 4;
#pragma unroll
        for (int i = 0; i < 8; ++i) {
            const int r = wid * 16 + 2 * i + lrow;
            selfAcc[i] += va[i].x * __log2f(va[i].x + EPSF)
                        + va[i].y * __log2f(va[i].y + EPSF);
            __nv_bfloat16 hx = __float2bfloat16(va[i].x);
            __nv_bfloat16 hy = __float2bfloat16(va[i].y);
            __nv_bfloat16 lx = __float2bfloat16(va[i].x - __bfloat162float(hx));
            __nv_bfloat16 ly = __float2bfloat16(va[i].y - __bfloat162float(hy));
            uint32_t ph = (uint32_t)__bfloat16_as_ushort(hx) | ((uint32_t)__bfloat16_as_ushort(hy) << 16);
            uint32_t pl = (uint32_t)__bfloat16_as_ushort(lx) | ((uint32_t)__bfloat16_as_ushort(ly) << 16);
            uint32_t swz  = (uint32_t)((r >> 1) & 3);
            uint32_t byte = (uint32_t)r * 64 + ((coff ^ swz) << 4) + within;
            *(uint32_t*)(smem + buf * 16384 + byte)        = ph;
            *(uint32_t*)(smem + buf * 16384 + 8192 + byte) = pl;
        }
    };
    auto issueB = [&](int s, int buf) {
        const char* src = reinterpret_cast<const char*>(g_qB) + (size_t)(cI * STAGES + s) * 8192;
        uint32_t dst = sB + buf * 8192 + tid * 16;
        CP_ASYNC16(dst, src + tid * 16);
        CP_ASYNC16(dst + 4096, src + tid * 16 + 4096);
    };

    // prologue
    loadA(0);
    issueB(0, 0);
    CP_COMMIT();
    storeA(0);
    CP_WAIT0();
    __syncthreads();

    for (int s = 0; s < STAGES; ++s) {
        const int buf = s & 1;
        const bool more = (s + 1 < STAGES);
        if (more) {
            loadA(s + 1);
            issueB(s + 1, buf ^ 1);
            CP_COMMIT();
        }

        const uint32_t aBase = sA + buf * 16384;
        const uint32_t bBase = sB + buf * 8192;
#pragma unroll
        for (int kh = 0; kh < 2; ++kh) {
            uint32_t bh[2][4], bl[2][4], ah[2][4], al[2][4];
#pragma unroll
            for (int nc = 0; nc < 2; ++nc) {
                uint32_t addr = bBase + (uint32_t)(kh * 16 + kB) * 128
                              + (uint32_t)(((wn * 4 + nc * 2 + cB) ^ swzB) << 4);
                LDSM_X4T(bh[nc], addr);
                LDSM_X4T(bl[nc], addr + 4096);
            }
#pragma unroll
            for (int mi = 0; mi < 2; ++mi) {
                const int R = wm * 32 + mi * 16;
                uint32_t addr = aBase + (uint32_t)(R + rowA) * 64
                              + (uint32_t)(((kh * 2 + cA) ^ swzA) << 4);
                LDSM_X4(ah[mi], addr);
                LDSM_X4(al[mi], addr + 8192);
            }
            // chain-major issue: same-accumulator spacing = 8 MMAs
#pragma unroll
            for (int mi = 0; mi < 2; ++mi)
#pragma unroll
                for (int nc = 0; nc < 2; ++nc) {
                    MMA16816(acc[mi][2 * nc],     ah[mi], bh[nc][0], bh[nc][1]);
                    MMA16816(acc[mi][2 * nc + 1], ah[mi], bh[nc][2], bh[nc][3]);
                }
#pragma unroll
            for (int mi = 0; mi < 2; ++mi)
#pragma unroll
                for (int nc = 0; nc < 2; ++nc) {
                    MMA16816(acc[mi][2 * nc],     ah[mi], bl[nc][0], bl[nc][1]);
                    MMA16816(acc[mi][2 * nc + 1], ah[mi], bl[nc][2], bl[nc][3]);
                }
#pragma unroll
            for (int mi = 0; mi < 2; ++mi)
#pragma unroll
                for (int nc = 0; nc < 2; ++nc) {
                    MMA16816(acc[mi][2 * nc],     al[mi], bh[nc][0], bh[nc][1]);
                    MMA16816(acc[mi][2 * nc + 1], al[mi], bh[nc][2], bh[nc][3]);
                }
        }

        if (more) storeA(buf ^ 1);
        CP_WAIT0();
        __syncthreads();
    }

    // ---- self-term: reduce 16 lanes sharing each row ----
#pragma unroll
    for (int i = 0; i < 8; ++i) {
        float v = selfAcc[i];
        v += __shfl_xor_sync(0xffffffffu, v, 1);
        v += __shfl_xor_sync(0xffffffffu, v, 2);
        v += __shfl_xor_sync(0xffffffffu, v, 4);
        v += __shfl_xor_sync(0xffffffffu, v, 8);
        if ((lane & 15) == 0)
            g_self[cI * K_A + kb + wid * 16 + 2 * i + lrow] = v * LN2F;
    }

    // ---- epilogue: transpose through smem, coalesced g_cross stores ----
    float* Csm = reinterpret_cast<float*>(smem);   // [64 q][128 m]
    const int g   = lane >> 2;
    const int tig = lane & 3;
#pragma unroll
    for (int mi = 0; mi < 2; ++mi) {
        const int r0 = wm * 32 + mi * 16 + g;
#pragma unroll
        for (int nh = 0; nh < 4; ++nh) {
            const int col = wn * 32 + nh * 8 + tig * 2;
            Csm[(col    ) * 128 + r0    ] = acc[mi][nh][0];
            Csm[(col + 1) * 128 + r0    ] = acc[mi][nh][1];
            Csm[(col    ) * 128 + r0 + 8] = acc[mi][nh][2];
            Csm[(col + 1) * 128 + r0 + 8] = acc[mi][nh][3];
        }
    }
    __syncthreads();
    {
        const int qq = tid >> 2;
        const int mb = (tid & 3) * 32;
        const float4* src = reinterpret_cast<const float4*>(Csm + qq * 128 + mb);
        float4* dst = reinterpret_cast<float4*>(g_cross + ((size_t)(cI * B_Q + qq)) * K_A + kb + mb);
#pragma unroll
        for (int j = 0; j < 8; ++j) dst[j] = src[j];
    }
}

// ---------------- Kernel C: fp64 combine + top-8 argmin + majority vote ----------------
__global__ void __launch_bounds__(256)
topk_kernel(const int* __restrict__ label, float* __restrict__ out) {
    __shared__ double kl[K_A];
    __shared__ double rv[256];
    __shared__ int    ri[256];
    const int b   = blockIdx.x;
    const int tid = threadIdx.x;

    for (int k = tid; k < K_A; k += 256) {
        double s = 0.0;
#pragma unroll
        for (int c = 0; c < DSPLIT; ++c)
            s += (double)g_self[c * K_A + k]
               - (double)g_cross[((size_t)(c * B_Q + b)) * K_A + k];
        kl[k] = s;   // = D * kl[b][k]
    }
    __syncthreads();

    int cnt1 = 0;
    for (int r = 0; r < KNN; ++r) {
        double bv = 1e300; int bi = K_A - 1;
        for (int k = tid; k < K_A; k += 256) {
            double v = kl[k];
            if (v < bv) { bv = v; bi = k; }
        }
        rv[tid] = bv; ri[tid] = bi;
        __syncthreads();
        for (int off = 128; off > 0; off >>= 1) {
            if (tid < off) {
                double v = rv[tid + off]; int i2 = ri[tid + off];
                if (v < rv[tid] || (v == rv[tid] && i2 < ri[tid])) { rv[tid] = v; ri[tid] = i2; }
            }
            __syncthreads();
        }
        int sel = ri[0];
        if (sel < 0)    sel = 0;
        if (sel >= K_A) sel = K_A - 1;
        cnt1 += label[sel];
        if (tid == 0) kl[sel] = 1e300;
        __syncthreads();
    }
    if (tid == 0) out[b] = (cnt1 > KNN / 2) ? 1.0f : 0.0f;
}

extern "C" void kernel_launch(void* const* d_in, const int* in_sizes, int n_in,
                              void* d_out, int out_size) {
    (void)in_sizes; (void)n_in; (void)out_size;
    const float* query  = (const float*)d_in[0];
    const float* anchor = (const float*)d_in[1];
    const int*   label  = (const int*)d_in[2];
    float* out = (float*)d_out;

    qlog_kernel<<<NTILES, 256>>>(query);
    dim3 g(K_A / KTILE, DSPLIT);
    gemm_kernel<<<g, 256>>>(anchor);
    topk_kernel<<<B_Q, 256>>>(label, out);
}

// round 14
// speedup vs baseline: 2.3211x; 1.1213x over previous
#include <cuda_runtime.h>
#include <cuda_fp16.h>
#include <cstdint>

#define D_DIM   50257
#define B_Q     64
#define K_A     4096
#define KNN     8
#define EPSF    1e-10f
#define LN2F    0.69314718055994530942f

#define DSPLIT  9
#define DTILE   32
#define STAGES  175                  // ceil(50257 / (9*32))
#define CHUNK_D (STAGES * DTILE)     // 5600
#define DPAD    (DSPLIT * CHUNK_D)   // 50400
#define NTILES  (DPAD / DTILE)       // 1575
#define KTILE   128

// ---- static device scratch ----
__device__ __align__(16) unsigned short g_qB[NTILES * 4096]; // 12.9MB: per 32-d tile [qh 4KB][ql 4KB], swizzled
__device__ float g_cross[DSPLIT * B_Q * K_A];                // 9.4MB partial cross sums
__device__ float g_self [DSPLIT * K_A];

__device__ __forceinline__ uint32_t smem_u32(const void* p) {
    uint32_t a;
    asm("{ .reg .u64 t; cvta.to.shared.u64 t, %1; cvt.u32.u64 %0, t; }" : "=r"(a) : "l"(p));
    return a;
}

#define CP_ASYNC16(dst, src) asm volatile("cp.async.cg.shared.global [%0], [%1], 16;" :: "r"(dst), "l"(src))
#define CP_COMMIT()          asm volatile("cp.async.commit_group;" ::: "memory")
#define CP_WAIT0()           asm volatile("cp.async.wait_group 0;" ::: "memory")

#define LDSM_X4(r, a) \
    asm volatile("ldmatrix.sync.aligned.m8n8.x4.shared.b16 {%0,%1,%2,%3}, [%4];" \
        : "=r"((r)[0]),"=r"((r)[1]),"=r"((r)[2]),"=r"((r)[3]) : "r"(a))
#define LDSM_X4T(r, a) \
    asm volatile("ldmatrix.sync.aligned.m8n8.x4.trans.shared.b16 {%0,%1,%2,%3}, [%4];" \
        : "=r"((r)[0]),"=r"((r)[1]),"=r"((r)[2]),"=r"((r)[3]) : "r"(a))

#define MMA16816F16(c, a, b0, b1) \
    asm volatile("mma.sync.aligned.m16n8k16.row.col.f32.f16.f16.f32 " \
        "{%0,%1,%2,%3}, {%4,%5,%6,%7}, {%8,%9}, {%0,%1,%2,%3};" \
        : "+f"((c)[0]),"+f"((c)[1]),"+f"((c)[2]),"+f"((c)[3]) \
        : "r"((a)[0]),"r"((a)[1]),"r"((a)[2]),"r"((a)[3]), "r"(b0),"r"(b1))

// ---------------- Kernel A: qlog -> fp16 hi/lo tiles, smem-staged coalesced output ----------------
// One block per 32-d tile. Output layout per tile (8KB): hi rows k=0..31 (128B of 64 n),
// 16B chunk c stored at c^(k&7); lo at +4096B. Matches GEMM's B-side ldmatrix swizzle.
#define QPAD 72
__global__ void __launch_bounds__(256)
qlog_kernel(const float* __restrict__ q) {
    __shared__ __align__(16) unsigned short sh[32 * QPAD];
    __shared__ __align__(16) unsigned short sl[32 * QPAD];
    const int t    = blockIdx.x;
    const int lane = threadIdx.x & 31;
    const int w    = threadIdx.x >> 5;
    const int d    = t * DTILE + lane;
    const bool v   = d < D_DIM;
#pragma unroll
    for (int i = 0; i < 8; ++i) {
        const int b = w * 8 + i;
        float x = 0.f;
        if (v) x = __log2f(q[(size_t)b * D_DIM + d] + EPSF) * LN2F;   // coalesced 128B reads
        __half h = __float2half(x);
        __half l = __float2half(x - __half2float(h));
        sh[lane * QPAD + b] = __half_as_ushort(h);
        sl[lane * QPAD + b] = __half_as_ushort(l);
    }
    __syncthreads();
    // write out: thread -> one 16B chunk; consecutive tid -> consecutive 16B (fully coalesced)
    const int k  = threadIdx.x >> 3;
    const int cs = threadIdx.x & 7;       // stored chunk
    const int c  = cs ^ (k & 7);          // source b-chunk (involution)
    uint4* tb = reinterpret_cast<uint4*>(g_qB + (size_t)t * 4096);
    tb[k * 8 + cs]       = *reinterpret_cast<const uint4*>(sh + k * QPAD + c * 8);
    tb[256 + k * 8 + cs] = *reinterpret_cast<const uint4*>(sl + k * QPAD + c * 8);
}

// ---------------- Kernel B: fp16 2-chain tensor-core GEMM + fused self-term ----------------
// smem 32KB: A [2 buf][128 r][32 k] fp16 (buf 8KB at 0/8192); B at +16384 [2 buf][hi|lo][32 k][64 n]
// Warp grid 4x2: warp tile 32(M) x 32(N). Chains: A*Qh + A*Ql.
__global__ void __launch_bounds__(256, 2)
gemm_kernel(const float* __restrict__ anchor) {
    __shared__ __align__(128) char smem[32768];
    const uint32_t sA = smem_u32(smem);
    const uint32_t sB = sA + 16384;

    const int tid  = threadIdx.x;
    const int lane = tid & 31;
    const int wid  = tid >> 5;
    const int wm   = wid >> 1;        // 0..3 : M quarter (32 rows)
    const int wn   = wid & 1;         // 0..1 : N half (32 cols)
    const int kb   = blockIdx.x * KTILE;
    const int cI   = blockIdx.y;
    const int dbase = cI * CHUNK_D;

    // loader mapping: warp owns rows wid*16..+15; lane: lrow = lane>>4, d-pair = lane&15
    const int lrow = lane >> 4;
    const int lcol = lane & 15;

    // ldmatrix lane constants
    const int rowA = lane & 15;
    const int cA   = lane >> 4;
    const int swzA = ((lane & 15) >> 1) & 3;
    const int kB   = lane & 15;
    const int cB   = lane >> 4;
    const int swzB = lane & 7;

    float acc[2][4][4];               // [mi][nh][frag]
#pragma unroll
    for (int mi = 0; mi < 2; ++mi)
#pragma unroll
        for (int nh = 0; nh < 4; ++nh)
#pragma unroll
            for (int r = 0; r < 4; ++r) acc[mi][nh][r] = 0.f;

    float selfAcc[8];
#pragma unroll
    for (int i = 0; i < 8; ++i) selfAcc[i] = 0.f;

    float2 va[8];

    auto loadA = [&](int s) {
        const int d0 = dbase + s * DTILE + 2 * lcol;
        const bool vx = d0 < D_DIM;
        const bool vy = d0 + 1 < D_DIM;
#pragma unroll
        for (int i = 0; i < 8; ++i) {
            const float* p = anchor + (size_t)(kb + wid * 16 + 2 * i + lrow) * D_DIM + d0;
            va[i].x = vx ? __ldg(p)     : 0.f;
            va[i].y = vy ? __ldg(p + 1) : 0.f;
        }
    };
    auto storeA = [&](int buf) {
        const uint32_t coff   = (uint32_t)(lcol >> 2);
        const uint32_t within = (uint32_t)(lcol & 3) * 4;
#pragma unroll
        for (int i = 0; i < 8; ++i) {
            const int r = wid * 16 + 2 * i + lrow;
            selfAcc[i] += va[i].x * __log2f(va[i].x + EPSF)
                        + va[i].y * __log2f(va[i].y + EPSF);
            __half hx = __float2half(va[i].x);
            __half hy = __float2half(va[i].y);
            uint32_t ph = (uint32_t)__half_as_ushort(hx) | ((uint32_t)__half_as_ushort(hy) << 16);
            uint32_t swz  = (uint32_t)((r >> 1) & 3);
            uint32_t byte = (uint32_t)r * 64 + ((coff ^ swz) << 4) + within;
            *(uint32_t*)(smem + buf * 8192 + byte) = ph;
        }
    };
    auto issueB = [&](int s, int buf) {
        const char* src = reinterpret_cast<const char*>(g_qB) + (size_t)(cI * STAGES + s) * 8192;
        uint32_t dst = sB + buf * 8192 + tid * 16;
        CP_ASYNC16(dst, src + tid * 16);
        CP_ASYNC16(dst + 4096, src + tid * 16 + 4096);
    };

    // prologue
    loadA(0);
    issueB(0, 0);
    CP_COMMIT();
    storeA(0);
    CP_WAIT0();
    __syncthreads();

    for (int s = 0; s < STAGES; ++s) {
        const int buf = s & 1;
        const bool more = (s + 1 < STAGES);
        if (more) {
            loadA(s + 1);
            issueB(s + 1, buf ^ 1);
            CP_COMMIT();
        }

        const uint32_t aBase = sA + buf * 8192;
        const uint32_t bBase = sB + buf * 8192;
#pragma unroll
        for (int kh = 0; kh < 2; ++kh) {
            uint32_t bh[2][4], bl[2][4], ah[2][4];
#pragma unroll
            for (int nc = 0; nc < 2; ++nc) {
                uint32_t addr = bBase + (uint32_t)(kh * 16 + kB) * 128
                              + (uint32_t)(((wn * 4 + nc * 2 + cB) ^ swzB) << 4);
                LDSM_X4T(bh[nc], addr);
                LDSM_X4T(bl[nc], addr + 4096);
            }
#pragma unroll
            for (int mi = 0; mi < 2; ++mi) {
                const int R = wm * 32 + mi * 16;
                uint32_t addr = aBase + (uint32_t)(R + rowA) * 64
                              + (uint32_t)(((kh * 2 + cA) ^ swzA) << 4);
                LDSM_X4(ah[mi], addr);
            }
            // chain-major issue: same-accumulator spacing = 8 MMAs
#pragma unroll
            for (int mi = 0; mi < 2; ++mi)
#pragma unroll
                for (int nc = 0; nc < 2; ++nc) {
                    MMA16816F16(acc[mi][2 * nc],     ah[mi], bh[nc][0], bh[nc][1]);
                    MMA16816F16(acc[mi][2 * nc + 1], ah[mi], bh[nc][2], bh[nc][3]);
                }
#pragma unroll
            for (int mi = 0; mi < 2; ++mi)
#pragma unroll
                for (int nc = 0; nc < 2; ++nc) {
                    MMA16816F16(acc[mi][2 * nc],     ah[mi], bl[nc][0], bl[nc][1]);
                    MMA16816F16(acc[mi][2 * nc + 1], ah[mi], bl[nc][2], bl[nc][3]);
                }
        }

        if (more) storeA(buf ^ 1);
        CP_WAIT0();
        __syncthreads();
    }

    // ---- self-term: reduce 16 lanes sharing each row ----
#pragma unroll
    for (int i = 0; i < 8; ++i) {
        float v = selfAcc[i];
        v += __shfl_xor_sync(0xffffffffu, v, 1);
        v += __shfl_xor_sync(0xffffffffu, v, 2);
        v += __shfl_xor_sync(0xffffffffu, v, 4);
        v += __shfl_xor_sync(0xffffffffu, v, 8);
        if ((lane & 15) == 0)
            g_self[cI * K_A + kb + wid * 16 + 2 * i + lrow] = v * LN2F;
    }

    // ---- epilogue: transpose through smem, coalesced g_cross stores ----
    float* Csm = reinterpret_cast<float*>(smem);   // [64 q][128 m] = 32KB
    const int g   = lane >> 2;
    const int tig = lane & 3;
#pragma unroll
    for (int mi = 0; mi < 2; ++mi) {
        const int r0 = wm * 32 + mi * 16 + g;
#pragma unroll
        for (int nh = 0; nh < 4; ++nh) {
            const int col = wn * 32 + nh * 8 + tig * 2;
            Csm[(col    ) * 128 + r0    ] = acc[mi][nh][0];
            Csm[(col + 1) * 128 + r0    ] = acc[mi][nh][1];
            Csm[(col    ) * 128 + r0 + 8] = acc[mi][nh][2];
            Csm[(col + 1) * 128 + r0 + 8] = acc[mi][nh][3];
        }
    }
    __syncthreads();
    {
        const int qq = tid >> 2;
        const int mb = (tid & 3) * 32;
        const float4* src = reinterpret_cast<const float4*>(Csm + qq * 128 + mb);
        float4* dst = reinterpret_cast<float4*>(g_cross + ((size_t)(cI * B_Q + qq)) * K_A + kb + mb);
#pragma unroll
        for (int j = 0; j < 8; ++j) dst[j] = src[j];
    }
}

// ---------------- Kernel C: fp64 combine + top-8 argmin + majority vote ----------------
__global__ void __launch_bounds__(256)
topk_kernel(const int* __restrict__ label, float* __restrict__ out) {
    __shared__ double kl[K_A];
    __shared__ double rv[256];
    __shared__ int    ri[256];
    const int b   = blockIdx.x;
    const int tid = threadIdx.x;

    for (int k = tid; k < K_A; k += 256) {
        double s = 0.0;
#pragma unroll
        for (int c = 0; c < DSPLIT; ++c)
            s += (double)g_self[c * K_A + k]
               - (double)g_cross[((size_t)(c * B_Q + b)) * K_A + k];
        kl[k] = s;   // = D * kl[b][k]
    }
    __syncthreads();

    int cnt1 = 0;
    for (int r = 0; r < KNN; ++r) {
        double bv = 1e300; int bi = K_A - 1;
        for (int k = tid; k < K_A; k += 256) {
            double v = kl[k];
            if (v < bv) { bv = v; bi = k; }
        }
        rv[tid] = bv; ri[tid] = bi;
        __syncthreads();
        for (int off = 128; off > 0; off >>= 1) {
            if (tid < off) {
                double v = rv[tid + off]; int i2 = ri[tid + off];
                if (v < rv[tid] || (v == rv[tid] && i2 < ri[tid])) { rv[tid] = v; ri[tid] = i2; }
            }
            __syncthreads();
        }
        int sel = ri[0];
        if (sel < 0)    sel = 0;
        if (sel >= K_A) sel = K_A - 1;
        cnt1 += label[sel];
        if (tid == 0) kl[sel] = 1e300;
        __syncthreads();
    }
    if (tid == 0) out[b] = (cnt1 > KNN / 2) ? 1.0f : 0.0f;
}

extern "C" void kernel_launch(void* const* d_in, const int* in_sizes, int n_in,
                              void* d_out, int out_size) {
    (void)in_sizes; (void)n_in; (void)out_size;
    const float* query  = (const float*)d_in[0];
    const float* anchor = (const float*)d_in[1];
    const int*   label  = (const int*)d_in[2];
    float* out = (float*)d_out;

    qlog_kernel<<<NTILES, 256>>>(query);
    dim3 g(K_A / KTILE, DSPLIT);
    gemm_kernel<<<g, 256>>>(anchor);
    topk_kernel<<<B_Q, 256>>>(label, out);
}

// round 15
// speedup vs baseline: 2.5065x; 1.0799x over previous
#include <cuda_runtime.h>
#include <cuda_fp16.h>
#include <cstdint>

#define D_DIM   50257
#define B_Q     64
#define K_A     4096
#define KNN     8
#define EPSF    1e-10f
#define LN2F    0.69314718055994530942f
#define MU      (-1.0f)              // global qlog mean: E[ln U(0,1)] = -1

#define DSPLIT  9
#define DTILE   64
#define STAGES  88                   // ceil(50257 / (9*64)) -> 9*88*64 = 50688
#define CHUNK_D (STAGES * DTILE)     // 5632
#define DPAD    (DSPLIT * CHUNK_D)   // 50688
#define NTILES  (DPAD / DTILE)       // 792
#define KTILE   128

// ---- static device scratch ----
// per 64-d tile: 8KB = 64 rows(k) x 128B(64 n fp16), 16B chunk c stored at c^(k&7)
__device__ __align__(16) unsigned short g_qB[NTILES * 4096];  // 6.4MB  (r = qlog - MU, fp16)
__device__ float g_cross[DSPLIT * B_Q * K_A];                 // 9.4MB  partial  sum a_h*r_h
__device__ float g_self [DSPLIT * K_A];                       //        partial  sum a*(ln a - MU)

__device__ __forceinline__ uint32_t smem_u32(const void* p) {
    uint32_t a;
    asm("{ .reg .u64 t; cvta.to.shared.u64 t, %1; cvt.u32.u64 %0, t; }" : "=r"(a) : "l"(p));
    return a;
}

#define CP_ASYNC16(dst, src) asm volatile("cp.async.cg.shared.global [%0], [%1], 16;" :: "r"(dst), "l"(src))
#define CP_COMMIT()          asm volatile("cp.async.commit_group;" ::: "memory")
#define CP_WAIT0()           asm volatile("cp.async.wait_group 0;" ::: "memory")

#define LDSM_X4(r, a) \
    asm volatile("ldmatrix.sync.aligned.m8n8.x4.shared.b16 {%0,%1,%2,%3}, [%4];" \
        : "=r"((r)[0]),"=r"((r)[1]),"=r"((r)[2]),"=r"((r)[3]) : "r"(a))
#define LDSM_X4T(r, a) \
    asm volatile("ldmatrix.sync.aligned.m8n8.x4.trans.shared.b16 {%0,%1,%2,%3}, [%4];" \
        : "=r"((r)[0]),"=r"((r)[1]),"=r"((r)[2]),"=r"((r)[3]) : "r"(a))

#define MMA16816F16(c, a, b0, b1) \
    asm volatile("mma.sync.aligned.m16n8k16.row.col.f32.f16.f16.f32 " \
        "{%0,%1,%2,%3}, {%4,%5,%6,%7}, {%8,%9}, {%0,%1,%2,%3};" \
        : "+f"((c)[0]),"+f"((c)[1]),"+f"((c)[2]),"+f"((c)[3]) \
        : "r"((a)[0]),"r"((a)[1]),"r"((a)[2]),"r"((a)[3]), "r"(b0),"r"(b1))

// ---------------- Kernel A: r = ln(q+eps) - MU -> fp16 tiles (64 k x 64 n, chunk^ (k&7)) ----------------
#define QPAD 72
__global__ void __launch_bounds__(256)
qlog_kernel(const float* __restrict__ q) {
    __shared__ __align__(16) unsigned short sr[64 * QPAD];
    const int t    = blockIdx.x;
    const int lane = threadIdx.x & 31;
    const int w    = threadIdx.x >> 5;
#pragma unroll
    for (int h = 0; h < 2; ++h) {
        const int d = t * DTILE + h * 32 + lane;
        const bool v = d < D_DIM;
#pragma unroll
        for (int i = 0; i < 8; ++i) {
            const int b = w * 8 + i;
            float r = 0.f;
            if (v) r = __log2f(q[(size_t)b * D_DIM + d] + EPSF) * LN2F - MU;  // coalesced reads
            sr[(h * 32 + lane) * QPAD + b] = __half_as_ushort(__float2half(r));
        }
    }
    __syncthreads();
    // repack: 64 rows x 8 chunks of 16B; thread handles rows tid>>3 and tid>>3 + 32
    uint4* tb = reinterpret_cast<uint4*>(g_qB + (size_t)t * 4096);
    const int cs = threadIdx.x & 7;
#pragma unroll
    for (int hh = 0; hh < 2; ++hh) {
        const int k = (threadIdx.x >> 3) + hh * 32;
        const int c = cs ^ (k & 7);
        tb[k * 8 + cs] = *reinterpret_cast<const uint4*>(sr + k * QPAD + c * 8);
    }
}

// ---------------- Kernel B: single-chain fp16 GEMM (A_h * r_h) + fused self-term ----------------
// smem: A [2 buf][128 r][128B] at 0 (buf 16KB), B [2 buf][64 k][128B] at 32768 (buf 8KB). 48KB total.
// Warp grid 4x2 (warp tile 32M x 32N). A swizzle: 16B chunk c stored at c^(row&7).
__global__ void __launch_bounds__(256, 2)
gemm_kernel(const float* __restrict__ anchor) {
    __shared__ __align__(128) char smem[49152];
    const uint32_t sA = smem_u32(smem);
    const uint32_t sB = sA + 32768;

    const int tid  = threadIdx.x;
    const int lane = tid & 31;
    const int wid  = tid >> 5;
    const int wm   = wid >> 1;        // 0..3 : 32-row M tile
    const int wn   = wid & 1;         // 0..1 : 32-col N tile
    const int kb   = blockIdx.x * KTILE;
    const int cI   = blockIdx.y;
    const int dbase = cI * CHUNK_D;

    // ldmatrix lane constants
    const int rowA = lane & 15;
    const int cA   = lane >> 4;
    const int kB   = lane & 15;
    const int cB   = lane >> 4;
    const int swzB = lane & 7;

    float acc[2][4][4];               // [mi][nh][frag]
#pragma unroll
    for (int mi = 0; mi < 2; ++mi)
#pragma unroll
        for (int nh = 0; nh < 4; ++nh)
#pragma unroll
            for (int r = 0; r < 4; ++r) acc[mi][nh][r] = 0.f;

    float selfAcc[16];                // per owned row (wid*16 + i), this lane's d-slice
#pragma unroll
    for (int i = 0; i < 16; ++i) selfAcc[i] = 0.f;

    float2 va[8];                     // one row-half in flight

    // loader: warp owns rows wid*16..+15; lane l covers float2 l (d = 2l..2l+1) of each row
    auto loadAh = [&](int s, int half) {
        const int d0 = dbase + s * DTILE + 2 * lane;
        const bool vx = d0 < D_DIM;
        const bool vy = d0 + 1 < D_DIM;
#pragma unroll
        for (int i = 0; i < 8; ++i) {
            const float* p = anchor + (size_t)(kb + wid * 16 + half * 8 + i) * D_DIM + d0;
            va[i].x = vx ? __ldg(p)     : 0.f;
            va[i].y = vy ? __ldg(p + 1) : 0.f;
        }
    };
    auto storeAh = [&](int buf, int half) {
#pragma unroll
        for (int i = 0; i < 8; ++i) {
            const int r = wid * 16 + half * 8 + i;
            // self' = a * (ln(a+eps) - MU); exact fp32, one accumulator per row-slice
            selfAcc[half * 8 + i] += va[i].x * (__log2f(va[i].x + EPSF) * LN2F - MU)
                                   + va[i].y * (__log2f(va[i].y + EPSF) * LN2F - MU);
            __half hx = __float2half(va[i].x);
            __half hy = __float2half(va[i].y);
            uint32_t ph = (uint32_t)__half_as_ushort(hx) | ((uint32_t)__half_as_ushort(hy) << 16);
            uint32_t byte = (uint32_t)r * 128 + ((((uint32_t)lane >> 2) ^ ((uint32_t)r & 7)) << 4)
                          + ((uint32_t)lane & 3) * 4;
            *(uint32_t*)(smem + buf * 16384 + byte) = ph;   // all lanes same row -> 32 banks
        }
    };
    auto issueB = [&](int s, int buf) {
        const char* src = reinterpret_cast<const char*>(g_qB) + (size_t)(cI * STAGES + s) * 8192;
        uint32_t dst = sB + buf * 8192 + tid * 16;
        CP_ASYNC16(dst, src + tid * 16);
        CP_ASYNC16(dst + 4096, src + tid * 16 + 4096);
    };

    // compute for one k16 group kh (0..3) of buffer buf
    auto computeKh = [&](int buf, int kh) {
        const uint32_t aBase = sA + buf * 16384;
        const uint32_t bBase = sB + buf * 8192;
        uint32_t bh[2][4], ah[2][4];
#pragma unroll
        for (int nc = 0; nc < 2; ++nc) {
            uint32_t addr = bBase + (uint32_t)(kh * 16 + kB) * 128
                          + (uint32_t)(((wn * 4 + nc * 2 + cB) ^ swzB) << 4);
            LDSM_X4T(bh[nc], addr);
        }
#pragma unroll
        for (int mi = 0; mi < 2; ++mi) {
            const int R = wm * 32 + mi * 16;
            const int rr = R + rowA;
            uint32_t addr = aBase + (uint32_t)rr * 128
                          + (uint32_t)(((kh * 2 + cA) ^ (rr & 7)) << 4);
            LDSM_X4(ah[mi], addr);
        }
#pragma unroll
        for (int mi = 0; mi < 2; ++mi)
#pragma unroll
            for (int nc = 0; nc < 2; ++nc) {
                MMA16816F16(acc[mi][2 * nc],     ah[mi], bh[nc][0], bh[nc][1]);
                MMA16816F16(acc[mi][2 * nc + 1], ah[mi], bh[nc][2], bh[nc][3]);
            }
    };

    // prologue: fill buffer 0
    loadAh(0, 0); storeAh(0, 0);
    loadAh(0, 1); storeAh(0, 1);
    issueB(0, 0);
    CP_COMMIT();
    CP_WAIT0();
    __syncthreads();

    for (int s = 0; s < STAGES; ++s) {
        const int buf = s & 1;
        const bool more = (s + 1 < STAGES);
        if (more) {
            issueB(s + 1, buf ^ 1);
            CP_COMMIT();
            loadAh(s + 1, 0);
        }
        computeKh(buf, 0);
        computeKh(buf, 1);
        if (more) {
            storeAh(buf ^ 1, 0);
            loadAh(s + 1, 1);
        }
        computeKh(buf, 2);
        computeKh(buf, 3);
        if (more) storeAh(buf ^ 1, 1);
        CP_WAIT0();
        __syncthreads();
    }

    // ---- self-term: reduce over all 32 lanes sharing each row ----
#pragma unroll
    for (int i = 0; i < 16; ++i) {
        float v = selfAcc[i];
        v += __shfl_xor_sync(0xffffffffu, v, 16);
        v += __shfl_xor_sync(0xffffffffu, v, 8);
        v += __shfl_xor_sync(0xffffffffu, v, 4);
        v += __shfl_xor_sync(0xffffffffu, v, 2);
        v += __shfl_xor_sync(0xffffffffu, v, 1);
        if (lane == 0)
            g_self[cI * K_A + kb + wid * 16 + i] = v;
    }

    // ---- epilogue: transpose through smem, coalesced g_cross stores ----
    float* Csm = reinterpret_cast<float*>(smem);   // [64 q][128 m] = 32KB
    const int g   = lane >> 2;
    const int tig = lane & 3;
#pragma unroll
    for (int mi = 0; mi < 2; ++mi) {
        const int r0 = wm * 32 + mi * 16 + g;
#pragma unroll
        for (int nh = 0; nh < 4; ++nh) {
            const int col = wn * 32 + nh * 8 + tig * 2;
            Csm[(col    ) * 128 + r0    ] = acc[mi][nh][0];
            Csm[(col + 1) * 128 + r0    ] = acc[mi][nh][1];
            Csm[(col    ) * 128 + r0 + 8] = acc[mi][nh][2];
            Csm[(col + 1) * 128 + r0 + 8] = acc[mi][nh][3];
        }
    }
    __syncthreads();
    {
        const int qq = tid >> 2;
        const int mb = (tid & 3) * 32;
        const float4* src = reinterpret_cast<const float4*>(Csm + qq * 128 + mb);
        float4* dst = reinterpret_cast<float4*>(g_cross + ((size_t)(cI * B_Q + qq)) * K_A + kb + mb);
#pragma unroll
        for (int j = 0; j < 8; ++j) dst[j] = src[j];
    }
}

// ---------------- Kernel C: fp64 combine + top-8 argmin + majority vote ----------------
__global__ void __launch_bounds__(256)
topk_kernel(const int* __restrict__ label, float* __restrict__ out) {
    __shared__ double kl[K_A];
    __shared__ double rv[256];
    __shared__ int    ri[256];
    const int b   = blockIdx.x;
    const int tid = threadIdx.x;

    for (int k = tid; k < K_A; k += 256) {
        double s = 0.0;
#pragma unroll
        for (int c = 0; c < DSPLIT; ++c)
            s += (double)g_self[c * K_A + k]
               - (double)g_cross[((size_t)(c * B_Q + b)) * K_A + k];
        kl[k] = s;   // = D * kl[b][k]  (self' and cross_r absorb the -MU centering exactly)
    }
    __syncthreads();

    int cnt1 = 0;
    for (int r = 0; r < KNN; ++r) {
        double bv = 1e300; int bi = K_A - 1;
        for (int k = tid; k < K_A; k += 256) {
            double v = kl[k];
            if (v < bv) { bv = v; bi = k; }
        }
        rv[tid] = bv; ri[tid] = bi;
        __syncthreads();
        for (int off = 128; off > 0; off >>= 1) {
            if (tid < off) {
                double v = rv[tid + off]; int i2 = ri[tid + off];
                if (v < rv[tid] || (v == rv[tid] && i2 < ri[tid])) { rv[tid] = v; ri[tid] = i2; }
            }
            __syncthreads();
        }
        int sel = ri[0];
        if (sel < 0)    sel = 0;
        if (sel >= K_A) sel = K_A - 1;
        cnt1 += label[sel];
        if (tid == 0) kl[sel] = 1e300;
        __syncthreads();
    }
    if (tid == 0) out[b] = (cnt1 > KNN / 2) ? 1.0f : 0.0f;
}

extern "C" void kernel_launch(void* const* d_in, const int* in_sizes, int n_in,
                              void* d_out, int out_size) {
    (void)in_sizes; (void)n_in; (void)out_size;
    const float* query  = (const float*)d_in[0];
    const float* anchor = (const float*)d_in[1];
    const int*   label  = (const int*)d_in[2];
    float* out = (float*)d_out;

    qlog_kernel<<<NTILES, 256>>>(query);
    dim3 g(K_A / KTILE, DSPLIT);
    gemm_kernel<<<g, 256>>>(anchor);
    topk_kernel<<<B_Q, 256>>>(label, out);
}